// round 7
// baseline (speedup 1.0000x reference)
#include <cuda_runtime.h>
#include <cuda_bf16.h>

#define NUM_NODES 5000
#define NUM_EDGES 80000
#define BS        2048      // BATCH * SEQ
#define OUTF      10
#define BKT_CAP   128       // max in-degree capacity (Poisson(16): P(>128) ~ 1e-60)
#define TPB       256
#define NFL4      (BS * 2 * OUTF / 4)      // 10240 float4 per node
#define SITERS    (NFL4 / TPB)             // 40 store iterations per node

// Scratch (allocation-free). g_cnt is zero-initialized at module load and
// self-cleaning: k_main resets it after consuming, so every call sees 0.
__device__ int g_cnt[NUM_NODES];
__device__ int g_bkt[NUM_NODES * BKT_CAP];

__global__ void k_bucket(const int* __restrict__ src, const int* __restrict__ dst) {
    int i = blockIdx.x * blockDim.x + threadIdx.x;
    if (i < NUM_EDGES) {
        int d = dst[i];
        int pos = atomicAdd(&g_cnt[d], 1);
        if (pos < BKT_CAP) g_bkt[d * BKT_CAP + pos] = src[i];
    }
}

// One block per PAIR of nodes; node0's stores are interleaved with node1's
// gathers so DRAM store traffic is in flight during L2 gather-wait windows.
__global__ __launch_bounds__(TPB) void k_main(const float* __restrict__ f,
                                              const float* __restrict__ w,
                                              float* __restrict__ out) {
    const int n0  = blockIdx.x * 2;
    const int n1  = n0 + 1;
    const int tid = threadIdx.x;

    __shared__ float sw[2 * OUTF];
    __shared__ float s_self[BS];
    __shared__ float s_mean[BS];
    __shared__ int   se0[BKT_CAP];
    __shared__ int   se1[BKT_CAP];

    if (tid < OUTF) { float wv = w[tid]; sw[tid] = wv; sw[tid + OUTF] = wv; }

    const int deg0 = min(g_cnt[n0], BKT_CAP);
    const int deg1 = min(g_cnt[n1], BKT_CAP);
    const float inv0 = (deg0 > 0) ? (1.0f / (float)deg0) : 0.0f;
    const float inv1 = (deg1 > 0) ? (1.0f / (float)deg1) : 0.0f;

    if (tid < deg0) se0[tid] = g_bkt[n0 * BKT_CAP + tid];
    if (tid < deg1) se1[tid] = g_bkt[n1 * BKT_CAP + tid];
    __syncthreads();
    if (tid == 0) { g_cnt[n0] = 0; g_cnt[n1] = 0; }

    // ---- gather node0 (2 float4 lanes per thread: tid, tid+TPB) ----
    float4 a0 = make_float4(0.f,0.f,0.f,0.f), b0 = a0;
    #pragma unroll 4
    for (int j = 0; j < deg0; j++) {
        const float4* row = (const float4*)(f + (size_t)se0[j] * BS);
        float4 v0 = __ldg(row + tid);
        float4 v1 = __ldg(row + tid + TPB);
        a0.x += v0.x; a0.y += v0.y; a0.z += v0.z; a0.w += v0.w;
        b0.x += v1.x; b0.y += v1.y; b0.z += v1.z; b0.w += v1.w;
    }
    {
        const float4* sr = (const float4*)(f + (size_t)n0 * BS);
        ((float4*)s_self)[tid]       = __ldg(sr + tid);
        ((float4*)s_self)[tid + TPB] = __ldg(sr + tid + TPB);
        ((float4*)s_mean)[tid]       = make_float4(a0.x*inv0, a0.y*inv0, a0.z*inv0, a0.w*inv0);
        ((float4*)s_mean)[tid + TPB] = make_float4(b0.x*inv0, b0.y*inv0, b0.z*inv0, b0.w*inv0);
    }
    __syncthreads();

    // ---- interleaved: store node0 + gather node1 ----
    float4 a1 = make_float4(0.f,0.f,0.f,0.f), b1 = a1;
    float4* ob0 = (float4*)out + (size_t)n0 * NFL4;
    int j = 0;
    #pragma unroll
    for (int c = 0; c < 4; c++) {
        // gather chunk: 4 edges of node1
        #pragma unroll
        for (int jj = 0; jj < 4; jj++) {
            if (j < deg1) {
                const float4* row = (const float4*)(f + (size_t)se1[j] * BS);
                float4 v0 = __ldg(row + tid);
                float4 v1 = __ldg(row + tid + TPB);
                a1.x += v0.x; a1.y += v0.y; a1.z += v0.z; a1.w += v0.w;
                b1.x += v1.x; b1.y += v1.y; b1.z += v1.z; b1.w += v1.w;
                j++;
            }
        }
        // store chunk: 10 iterations of node0's output
        #pragma unroll
        for (int i = 0; i < SITERS / 4; i++) {
            int idx = (c * (SITERS / 4) + i) * TPB + tid;
            int bs  = idx / 5;
            int c0  = (idx % 5) * 4;
            float s = s_self[bs];
            float m = s_mean[bs];
            float4 r;
            { int cc = c0 + 0; float bb = (cc < OUTF) ? s : m; r.x = fmaxf(bb * sw[cc], 0.0f); }
            { int cc = c0 + 1; float bb = (cc < OUTF) ? s : m; r.y = fmaxf(bb * sw[cc], 0.0f); }
            { int cc = c0 + 2; float bb = (cc < OUTF) ? s : m; r.z = fmaxf(bb * sw[cc], 0.0f); }
            { int cc = c0 + 3; float bb = (cc < OUTF) ? s : m; r.w = fmaxf(bb * sw[cc], 0.0f); }
            __stcs(ob0 + idx, r);
        }
    }
    // remaining node1 edges (deg1 > 16)
    #pragma unroll 4
    for (; j < deg1; j++) {
        const float4* row = (const float4*)(f + (size_t)se1[j] * BS);
        float4 v0 = __ldg(row + tid);
        float4 v1 = __ldg(row + tid + TPB);
        a1.x += v0.x; a1.y += v0.y; a1.z += v0.z; a1.w += v0.w;
        b1.x += v1.x; b1.y += v1.y; b1.z += v1.z; b1.w += v1.w;
    }
    float4 self1a, self1b;
    {
        const float4* sr = (const float4*)(f + (size_t)n1 * BS);
        self1a = __ldg(sr + tid);
        self1b = __ldg(sr + tid + TPB);
    }
    __syncthreads();   // all reads of node0's s_self/s_mean complete
    ((float4*)s_self)[tid]       = self1a;
    ((float4*)s_self)[tid + TPB] = self1b;
    ((float4*)s_mean)[tid]       = make_float4(a1.x*inv1, a1.y*inv1, a1.z*inv1, a1.w*inv1);
    ((float4*)s_mean)[tid + TPB] = make_float4(b1.x*inv1, b1.y*inv1, b1.z*inv1, b1.w*inv1);
    __syncthreads();

    // ---- store node1 ----
    float4* ob1 = (float4*)out + (size_t)n1 * NFL4;
    #pragma unroll
    for (int it = 0; it < SITERS; it++) {
        int idx = it * TPB + tid;
        int bs  = idx / 5;
        int c0  = (idx % 5) * 4;
        float s = s_self[bs];
        float m = s_mean[bs];
        float4 r;
        { int cc = c0 + 0; float bb = (cc < OUTF) ? s : m; r.x = fmaxf(bb * sw[cc], 0.0f); }
        { int cc = c0 + 1; float bb = (cc < OUTF) ? s : m; r.y = fmaxf(bb * sw[cc], 0.0f); }
        { int cc = c0 + 2; float bb = (cc < OUTF) ? s : m; r.z = fmaxf(bb * sw[cc], 0.0f); }
        { int cc = c0 + 3; float bb = (cc < OUTF) ? s : m; r.w = fmaxf(bb * sw[cc], 0.0f); }
        __stcs(ob1 + idx, r);
    }
}

extern "C" void kernel_launch(void* const* d_in, const int* in_sizes, int n_in,
                              void* d_out, int out_size) {
    const float* features = (const float*)d_in[0];
    const float* weight   = (const float*)d_in[1];
    const int*   edge_src = (const int*)d_in[2];
    const int*   edge_dst = (const int*)d_in[3];
    float*       out      = (float*)d_out;

    k_bucket<<<(NUM_EDGES + 255) / 256, 256>>>(edge_src, edge_dst);
    k_main<<<NUM_NODES / 2, TPB>>>(features, weight, out);
}